// round 15
// baseline (speedup 1.0000x reference)
#include <cuda_runtime.h>
#include <cuda_bf16.h>
#include <cstdint>

#define NLEV 4
#define MAXS 792
#define NTHREADS 256
#define CPG 8          // chunks (of 32 samples) per warp-group

// Packed table: level sizes 36/72/216/792 -> offsets 0/36/108/324, 1116 float2 (8.9KB)
#define T_TOT 1116

// R14: level-per-warp split. Each warp owns one level for 32-sample chunks;
// 4 warps = one group covering all levels. Depth-1 register pipeline over
// chunks (manually 2-unrolled). Target: <=64 regs -> 4 blocks/SM -> 32 warps.
__global__ __launch_bounds__(NTHREADS, 4) void heal_encoding_lvlwarp(
    const float2* __restrict__ params2,      // [NLEV, MAXS] float2
    const float2* __restrict__ pixel_ll,     // [NLEV, B]
    const float2* __restrict__ neigh_ll,     // [NLEV, 8, B]
    const int*    __restrict__ pixel_idx,    // [NLEV, B]
    const int*    __restrict__ neigh_idx,    // [NLEV, 8, B]
    float*        __restrict__ out,          // [B, 8]  out[b, l + 4f]
    int B)
{
    __shared__ float2 tab[T_TOT];

    const int tid  = threadIdx.x;
    const int wid  = tid >> 5;
    const int lane = tid & 31;
    const int lvl  = wid & 3;                       // this warp's level
    const int gid  = blockIdx.x * 2 + (wid >> 2);   // global group id

    const int nchunks = B >> 5;                     // full 32-sample chunks
    int mychunks = nchunks - gid * CPG;
    if (mychunks < 0) mychunks = 0;
    if (mychunks > CPG) mychunks = CPG;
    const int gstart = gid * CPG;                   // first chunk of this group

    const int toff = (lvl == 3) ? 324 : ((lvl == 2) ? 108 : lvl * 36);

    // streamed-input base pointers for this warp's level
    const int*    nip = neigh_idx + (size_t)lvl * 8 * B;
    const float2* nlp = neigh_ll  + (size_t)lvl * 8 * B;
    const int*    pip = pixel_idx + (size_t)lvl * B;
    const float2* plp = pixel_ll  + (size_t)lvl * B;

    // double buffers (registers; statically indexed via manual 2-unroll)
    int    niA[8], niB[8];
    float2 nlA[8], nlB[8];
    int    pA, pB;
    float2 plA, plB;

    // ---- prologue: issue chunk 0 loads BEFORE table copy (covered by it) ----
    {
        const int c0 = (mychunks > 0) ? gstart : 0;   // safe addr if idle
        const int b0 = (c0 << 5) + lane;
#pragma unroll
        for (int j = 0; j < 8; j++) niA[j] = __ldcs(nip + (size_t)j * B + b0);
#pragma unroll
        for (int j = 0; j < 8; j++) nlA[j] = __ldcs(nlp + (size_t)j * B + b0);
        pA  = __ldcs(pip + b0);
        plA = __ldcs(plp + b0);
    }

    // ---- table copy + barrier ----
    {
        const int tsz[NLEV]   = {36, 72, 216, 792};
        const int toffs[NLEV] = {0, 36, 108, 324};
#pragma unroll
        for (int l = 0; l < NLEV; l++)
            for (int i = tid; i < tsz[l]; i += NTHREADS)
                tab[toffs[l] + i] = params2[l * MAXS + i];
    }
    __syncthreads();

#define LOAD_CHUNK(c, ni, nl, pp, pll)                                   \
    do {                                                                 \
        const int bb = (((gstart) + (c)) << 5) + lane;                   \
        _Pragma("unroll")                                                \
        for (int j = 0; j < 8; j++) ni[j] = __ldcs(nip + (size_t)j * B + bb); \
        _Pragma("unroll")                                                \
        for (int j = 0; j < 8; j++) nl[j] = __ldcs(nlp + (size_t)j * B + bb); \
        pp  = __ldcs(pip + bb);                                          \
        pll = __ldcs(plp + bb);                                          \
    } while (0)

#define COMPUTE_STORE(c, ni, nl, pp, pll)                                \
    do {                                                                 \
        const float2 r = tab[toff + (pp)];                               \
        float s0 = r.x, s1 = r.y;                                        \
        _Pragma("unroll")                                                \
        for (int j = 0; j < 8; j++) {                                    \
            const int    n  = ni[j];                                     \
            const float2 ll = nl[j];                                     \
            const float dphi = ll.y - (pll).y;                           \
            const float dth  = ll.x - (pll).x;                           \
            float w = rsqrtf(fmaf(dphi, dphi, dth * dth));               \
            w = (n >= 0) ? w : 0.0f;                                     \
            const float2 v = tab[toff + (n >= 0 ? n : 0)];               \
            s0 = fmaf(w, v.x, s0);                                       \
            s1 = fmaf(w, v.y, s1);                                       \
        }                                                                \
        const int bb = (((gstart) + (c)) << 5) + lane;                   \
        __stcs(out + (size_t)bb * 8 + lvl,     s0);                      \
        __stcs(out + (size_t)bb * 8 + 4 + lvl, s1);                      \
    } while (0)

    int c = 0;
    while (c < mychunks) {
        // even chunk: buffer A live, prefetch into B
        if (c + 1 < mychunks) LOAD_CHUNK(c + 1, niB, nlB, pB, plB);
        COMPUTE_STORE(c, niA, nlA, pA, plA);
        c++;
        if (c >= mychunks) break;
        // odd chunk: buffer B live, prefetch into A
        if (c + 1 < mychunks) LOAD_CHUNK(c + 1, niA, nlA, pA, plA);
        COMPUTE_STORE(c, niB, nlB, pB, plB);
        c++;
    }
#undef LOAD_CHUNK
#undef COMPUTE_STORE

    // ---- tail: samples beyond nchunks*32 (B not multiple of 32), last block ----
    const int tail_start = nchunks << 5;
    if (blockIdx.x == gridDim.x - 1 && tail_start < B) {
        for (int b = tail_start + tid; b < B; b += NTHREADS) {
            float a0[NLEV], a1[NLEV];
#pragma unroll
            for (int l = 0; l < NLEV; l++) {
                const int toffs = (l == 3) ? 324 : ((l == 2) ? 108 : l * 36);
                int    ni[8];
                float2 nl[8];
#pragma unroll
                for (int j = 0; j < 8; j++)
                    ni[j] = __ldcs(neigh_idx + (size_t)(l * 8 + j) * B + b);
#pragma unroll
                for (int j = 0; j < 8; j++)
                    nl[j] = __ldcs(neigh_ll + (size_t)(l * 8 + j) * B + b);
                const int    pp = __ldcs(pixel_idx + (size_t)l * B + b);
                const float2 pl = __ldcs(pixel_ll + (size_t)l * B + b);
                const float2 r  = tab[toffs + pp];
                float s0 = r.x, s1 = r.y;
#pragma unroll
                for (int j = 0; j < 8; j++) {
                    const float dphi = nl[j].y - pl.y;
                    const float dth  = nl[j].x - pl.x;
                    float w = rsqrtf(fmaf(dphi, dphi, dth * dth));
                    w = (ni[j] >= 0) ? w : 0.0f;
                    const float2 v = tab[toffs + (ni[j] >= 0 ? ni[j] : 0)];
                    s0 = fmaf(w, v.x, s0);
                    s1 = fmaf(w, v.y, s1);
                }
                a0[l] = s0; a1[l] = s1;
            }
            float4* op = reinterpret_cast<float4*>(out + (size_t)b * 8);
            __stcs(op,     make_float4(a0[0], a0[1], a0[2], a0[3]));
            __stcs(op + 1, make_float4(a1[0], a1[1], a1[2], a1[3]));
        }
    }
}

extern "C" void kernel_launch(void* const* d_in, const int* in_sizes, int n_in,
                              void* d_out, int out_size)
{
    // metadata order: params, pixel_latlon, neigh_latlon, pixel_index, neigh_index
    const float2* params2   = (const float2*)d_in[0];
    const float2* pixel_ll  = (const float2*)d_in[1];
    const float2* neigh_ll  = (const float2*)d_in[2];
    const int*    pixel_idx = (const int*)d_in[3];
    const int*    neigh_idx = (const int*)d_in[4];
    float*        out       = (float*)d_out;

    const int B = in_sizes[3] / NLEV;   // pixel_index has NLEV*B elements

    const int nchunks = B >> 5;
    int grid = (nchunks + 2 * CPG - 1) / (2 * CPG);
    if (grid < 1) grid = 1;
    heal_encoding_lvlwarp<<<grid, NTHREADS>>>(
        params2, pixel_ll, neigh_ll, pixel_idx, neigh_idx, out, B);
}

// round 16
// speedup vs baseline: 1.1779x; 1.1779x over previous
#include <cuda_runtime.h>
#include <cuda_bf16.h>
#include <cstdint>

#define NLEV 4
#define MAXS 792
#define NTHREADS 256
#define NBLOCKS 444   // 148 SMs x 3 blocks/SM

// Packed table: level sizes 36/72/216/792 -> offsets 0/36/108/324, 1116 float2 (8.9KB)
#define T_TOT 1116

// R15: persistent grid-stride version of the winning depth-1 register pipeline.
// The pipeline runs continuously across sample boundaries (level 3 of sample k
// prefetches level 0 of sample k+1), so fill/drain happens once per kernel,
// not once per 256-sample block; table loads drop 3907 -> 444.
__global__ __launch_bounds__(NTHREADS, 3) void heal_encoding_persistpipe(
    const float2* __restrict__ params2,      // [NLEV, MAXS] float2
    const float2* __restrict__ pixel_ll,     // [NLEV, B]
    const float2* __restrict__ neigh_ll,     // [NLEV, 8, B]
    const int*    __restrict__ pixel_idx,    // [NLEV, B]
    const int*    __restrict__ neigh_idx,    // [NLEV, 8, B]
    float*        __restrict__ out,          // [B, 8]  out[b, 4f+l]
    int B)
{
    __shared__ float2 tab[T_TOT];
    __shared__ int    toff_s[NLEV];

    const int gtid    = blockIdx.x * NTHREADS + threadIdx.x;
    const int gstride = gridDim.x * NTHREADS;

    // double-buffered per-level inputs (registers, statically indexed)
    int    nidx[2][8];
    float2 nll [2][8];
    int    p   [2];
    float2 pl  [2];

    // ---- prologue: issue (sample gtid, level 0) loads BEFORE table copy ----
    {
        const int b0 = (gtid < B) ? gtid : 0;
#pragma unroll
        for (int j = 0; j < 8; j++)
            nidx[0][j] = __ldcs(neigh_idx + (size_t)j * B + b0);
#pragma unroll
        for (int j = 0; j < 8; j++)
            nll[0][j]  = __ldcs(neigh_ll  + (size_t)j * B + b0);
        p[0]  = __ldcs(pixel_idx + b0);
        pl[0] = __ldcs(pixel_ll  + b0);
    }

    // ---- table copy + barrier (covers prologue load latency) ----
    {
        const int tsz[NLEV]  = {36, 72, 216, 792};
        const int toff[NLEV] = {0, 36, 108, 324};
        if (threadIdx.x < NLEV) toff_s[threadIdx.x] = toff[threadIdx.x];
#pragma unroll
        for (int l = 0; l < NLEV; l++)
            for (int i = threadIdx.x; i < tsz[l]; i += NTHREADS)
                tab[toff[l] + i] = params2[l * MAXS + i];
    }
    __syncthreads();

    float acc0[NLEV], acc1[NLEV];

    for (int b = gtid; b < B; b += gstride) {
        const int  bn        = b + gstride;       // next sample for this thread
        const bool have_next = (bn < B);
        const int  bnl       = have_next ? bn : b;  // safe prefetch address

#pragma unroll
        for (int l = 0; l < NLEV; l++) {
            const int cur = l & 1;                // 4 items/sample -> parity stable
            const int nxt = cur ^ 1;

            // prefetch the next item: (b, l+1) or (bn, 0)
            const int  pl_lvl = (l + 1 < NLEV) ? (l + 1) : 0;
            const int  pl_b   = (l + 1 < NLEV) ? b : bnl;
            const bool do_pf  = (l + 1 < NLEV) || have_next;
            if (do_pf) {
#pragma unroll
                for (int j = 0; j < 8; j++)
                    nidx[nxt][j] = __ldcs(neigh_idx + (size_t)(pl_lvl * 8 + j) * B + pl_b);
#pragma unroll
                for (int j = 0; j < 8; j++)
                    nll[nxt][j]  = __ldcs(neigh_ll  + (size_t)(pl_lvl * 8 + j) * B + pl_b);
                p[nxt]  = __ldcs(pixel_idx + (size_t)pl_lvl * B + pl_b);
                pl[nxt] = __ldcs(pixel_ll  + (size_t)pl_lvl * B + pl_b);
            }

            // compute (b, l) from buffer cur
            const int    to = toff_s[l];
            const float2 P  = pl[cur];
            const float2 r  = tab[to + p[cur]];
            float s0 = r.x, s1 = r.y;
#pragma unroll
            for (int j = 0; j < 8; j++) {
                const int    n  = nidx[cur][j];
                const float2 ll = nll[cur][j];
                const float dphi = ll.y - P.y;
                const float dth  = ll.x - P.x;
                float w = rsqrtf(fmaf(dphi, dphi, dth * dth));
                w = (n >= 0) ? w : 0.0f;
                const float2 v = tab[to + (n >= 0 ? n : 0)];
                s0 = fmaf(w, v.x, s0);
                s1 = fmaf(w, v.y, s1);
            }
            acc0[l] = s0;
            acc1[l] = s1;
        }

        // out[b, 4f + l]: 8 contiguous floats -> two streaming float4 stores
        float4* op = reinterpret_cast<float4*>(out + (size_t)b * 8);
        __stcs(op,     make_float4(acc0[0], acc0[1], acc0[2], acc0[3]));
        __stcs(op + 1, make_float4(acc1[0], acc1[1], acc1[2], acc1[3]));
    }
}

extern "C" void kernel_launch(void* const* d_in, const int* in_sizes, int n_in,
                              void* d_out, int out_size)
{
    // metadata order: params, pixel_latlon, neigh_latlon, pixel_index, neigh_index
    const float2* params2   = (const float2*)d_in[0];
    const float2* pixel_ll  = (const float2*)d_in[1];
    const float2* neigh_ll  = (const float2*)d_in[2];
    const int*    pixel_idx = (const int*)d_in[3];
    const int*    neigh_idx = (const int*)d_in[4];
    float*        out       = (float*)d_out;

    const int B = in_sizes[3] / NLEV;   // pixel_index has NLEV*B elements

    heal_encoding_persistpipe<<<NBLOCKS, NTHREADS>>>(
        params2, pixel_ll, neigh_ll, pixel_idx, neigh_idx, out, B);
}